// round 10
// baseline (speedup 1.0000x reference)
#include <cuda_runtime.h>
#include <cuda_bf16.h>
#include <cstdint>

// Problem constants
#define BB    256
#define AA    5
#define TT    64
#define NINp  4
#define NHID  256
#define HH    1280
#define H4    5120
#define STEPS 63

// ---------------- persistent device scratch (allocation-free) ----------------
__device__ float g_h[2 * BB * HH];       // LSTM hidden states (2 layers)
__device__ float g_c[2 * BB * HH];       // LSTM cell states
__device__ float g_x1[BB * AA * NHID];   // mlp1_1 output  [1280,256]
__device__ float g_xin[BB * HH];         // current activation [256,1280]
__device__ float g_y[BB * HH];           // mlp2_1 output
__device__ float g_gx[BB * H4];          // gates from input GEMM
__device__ float g_gh[BB * H4];          // gates from hidden GEMM
__device__ float g_ins[BB * AA * NINp];  // this step's network input
__device__ float g_prev[BB * AA * NINp]; // previous step's output

__device__ __forceinline__ float sigmoidf_(float x) { return 1.0f / (1.0f + expf(-x)); }

// ---------------- state reset (must run every kernel_launch) ----------------
__global__ void zero_state_kernel() {
    int idx = blockIdx.x * blockDim.x + threadIdx.x;
    if (idx < 2 * BB * HH) { g_h[idx] = 0.0f; g_c[idx] = 0.0f; }
    if (idx < BB * AA * NINp) g_prev[idx] = 0.0f;
}

// ---------------- input select + mlp1_1 (K=4, tiny) ----------------
// grid: 1280 blocks (one per (b,a) row), 256 threads (one per NHID col)
__global__ void select_mlp1_kernel(const float* __restrict__ inputs,
                                   const float* __restrict__ w1_1,
                                   const float* __restrict__ b1_1,
                                   const int*   __restrict__ ps_ptr,
                                   int t) {
    int row = blockIdx.x;   // b*5 + a
    int c   = threadIdx.x;  // 0..255
    __shared__ float ins_s[NINp];
    if (c < NINp) {
        int ps = ps_ptr[0];
        // robust against the scalar being stored as float bits
        if (ps < 1 || ps > 1000000) ps = (int)__int_as_float(ps);
        if (ps < 1) ps = 1;
        float v;
        if ((t % ps) == 0) v = inputs[(row * TT + t) * NINp + c];
        else               v = g_prev[row * NINp + c];
        ins_s[c] = v;
        g_ins[row * NINp + c] = v;
    }
    __syncthreads();
    float acc = b1_1[c];
#pragma unroll
    for (int k = 0; k < NINp; k++) acc = fmaf(ins_s[k], w1_1[c * NINp + k], acc);
    g_x1[row * NHID + c] = fmaxf(acc, 0.0f);
}

// ---------------- generic fp32 GEMM: C = act(A @ B^T + bias) ----------------
// A: [M,K] row-major   B: [N,K] row-major   C: [M,N]
// blockIdx.z selects operand set 0/1 (dual GEMM fused into one launch so
// both LSTM matmuls share the chip in a single wave).
// Tile 64x64, BK=16, 128 threads, per-thread 4x8 register tile.
#define GBM 64
#define GBN 64
#define GBK 16

__global__ __launch_bounds__(128)
void gemm_dual_kernel(const float* __restrict__ A0, const float* __restrict__ B0,
                      const float* __restrict__ bias0, float* __restrict__ C0,
                      const float* __restrict__ A1, const float* __restrict__ B1,
                      const float* __restrict__ bias1, float* __restrict__ C1,
                      int N, int K, int relu) {
    const float* A;  const float* Bm; const float* bias; float* C;
    if (blockIdx.z == 0) { A = A0; Bm = B0; bias = bias0; C = C0; }
    else                 { A = A1; Bm = B1; bias = bias1; C = C1; }

    const int nb = blockIdx.x * GBN;
    const int mb = blockIdx.y * GBM;

    __shared__ __align__(16) float As[GBK][GBM + 4];  // k-major, padded
    __shared__ __align__(16) float Bs[GBK][GBN + 4];

    const int tid = threadIdx.x;           // 0..127
    const int tn  = tid & 7;               // 8 col groups
    const int tm  = tid >> 3;              // 16 row groups
    const int m0  = tm * 4;                // thread's 4 rows
    const int n0  = tn * 8;                // thread's 8 cols

    float acc[4][8];
#pragma unroll
    for (int i = 0; i < 4; i++)
#pragma unroll
        for (int j = 0; j < 8; j++) acc[i][j] = 0.0f;

    for (int kt = 0; kt < K; kt += GBK) {
        // load 64x16 A-tile and 64x16 B-tile (each 256 float4, 2 per thread)
#pragma unroll
        for (int it = 0; it < 2; ++it) {
            int f   = it * 128 + tid;
            int row = f >> 2;
            int k4  = (f & 3) << 2;
            float4 va = *reinterpret_cast<const float4*>(A  + (size_t)(mb + row) * K + kt + k4);
            As[k4 + 0][row] = va.x; As[k4 + 1][row] = va.y;
            As[k4 + 2][row] = va.z; As[k4 + 3][row] = va.w;
            float4 vb = *reinterpret_cast<const float4*>(Bm + (size_t)(nb + row) * K + kt + k4);
            Bs[k4 + 0][row] = vb.x; Bs[k4 + 1][row] = vb.y;
            Bs[k4 + 2][row] = vb.z; Bs[k4 + 3][row] = vb.w;
        }
        __syncthreads();
#pragma unroll
        for (int k = 0; k < GBK; ++k) {
            float4 a4 = *reinterpret_cast<const float4*>(&As[k][m0]);
            float4 b4 = *reinterpret_cast<const float4*>(&Bs[k][n0]);
            float4 b5 = *reinterpret_cast<const float4*>(&Bs[k][n0 + 4]);
            float a[4] = {a4.x, a4.y, a4.z, a4.w};
            float b[8] = {b4.x, b4.y, b4.z, b4.w, b5.x, b5.y, b5.z, b5.w};
#pragma unroll
            for (int i = 0; i < 4; i++)
#pragma unroll
                for (int j = 0; j < 8; j++)
                    acc[i][j] = fmaf(a[i], b[j], acc[i][j]);
        }
        __syncthreads();
    }

    // epilogue
    float bv[8];
#pragma unroll
    for (int j = 0; j < 8; j++) bv[j] = bias ? bias[nb + n0 + j] : 0.0f;
#pragma unroll
    for (int i = 0; i < 4; i++) {
        float* crow = C + (size_t)(mb + m0 + i) * N + nb + n0;
#pragma unroll
        for (int j = 0; j < 8; j++) {
            float v = acc[i][j] + bv[j];
            if (relu) v = fmaxf(v, 0.0f);
            crow[j] = v;
        }
    }
}

// ---------------- LSTM gate pointwise ----------------
// gates = g_gx + g_gh, PyTorch order i,f,g,o along N
__global__ void lstm_pointwise_kernel(int l) {
    int idx = blockIdx.x * blockDim.x + threadIdx.x;  // < BB*HH
    int m = idx / HH;
    int j = idx - m * HH;
    size_t gb = (size_t)m * H4 + j;
    float gi = g_gx[gb]          + g_gh[gb];
    float gf = g_gx[gb + HH]     + g_gh[gb + HH];
    float gg = g_gx[gb + 2 * HH] + g_gh[gb + 2 * HH];
    float go = g_gx[gb + 3 * HH] + g_gh[gb + 3 * HH];
    int off = l * BB * HH + idx;
    float cn = sigmoidf_(gf) * g_c[off] + sigmoidf_(gi) * tanhf(gg);
    float hn = sigmoidf_(go) * tanhf(cn);
    g_c[off]  = cn;
    g_h[off]  = hn;
    g_xin[idx] = hn;   // input to next layer / mlp2
}

// ---------------- mlp2_2 + residual + output ----------------
// one warp per (m,n) output; 256*20 = 5120 warps
__global__ void final_kernel(const float* __restrict__ w2_2,
                             const float* __restrict__ b2_2,
                             float* __restrict__ out, int t) {
    int gtid = blockIdx.x * blockDim.x + threadIdx.x;
    int w    = gtid >> 5;
    int lane = gtid & 31;
    if (w >= BB * 20) return;
    int m = w / 20;
    int n = w - m * 20;
    const float* yr = g_y  + (size_t)m * HH;
    const float* wr = w2_2 + (size_t)n * HH;
    float acc = 0.0f;
#pragma unroll 8
    for (int k = lane; k < HH; k += 32) acc = fmaf(yr[k], wr[k], acc);
#pragma unroll
    for (int s = 16; s; s >>= 1) acc += __shfl_xor_sync(0xffffffffu, acc, s);
    if (lane == 0) {
        float v = acc + b2_2[n] + g_ins[m * 20 + n];
        int a  = n >> 2;
        int nn = n & 3;
        out[((m * AA + a) * STEPS + t) * NINp + nn] = v;
        g_prev[m * 20 + n] = v;
    }
}

// ---------------- host launcher (graph-capturable, allocation-free) ----------------
extern "C" void kernel_launch(void* const* d_in, const int* in_sizes, int n_in,
                              void* d_out, int out_size) {
    const float* inputs = (const float*)d_in[0];
    const float* w1_1   = (const float*)d_in[1];
    const float* b1_1   = (const float*)d_in[2];
    const float* w1_2   = (const float*)d_in[3];
    const float* b1_2   = (const float*)d_in[4];
    const float* w_ih   = (const float*)d_in[5];
    const float* w_hh   = (const float*)d_in[6];
    const float* b_ih   = (const float*)d_in[7];
    const float* b_hh   = (const float*)d_in[8];
    const float* w2_1   = (const float*)d_in[9];
    const float* b2_1   = (const float*)d_in[10];
    const float* w2_2   = (const float*)d_in[11];
    const float* b2_2   = (const float*)d_in[12];
    const int*   ps     = (const int*)d_in[13];
    float* out = (float*)d_out;

    float *ph, *pc, *px1, *pxin, *py, *pgx, *pgh;
    cudaGetSymbolAddress((void**)&ph,   g_h);
    cudaGetSymbolAddress((void**)&pc,   g_c);
    cudaGetSymbolAddress((void**)&px1,  g_x1);
    cudaGetSymbolAddress((void**)&pxin, g_xin);
    cudaGetSymbolAddress((void**)&py,   g_y);
    cudaGetSymbolAddress((void**)&pgx,  g_gx);
    cudaGetSymbolAddress((void**)&pgh,  g_gh);

    // reset recurrent state every launch (deterministic across graph replays)
    zero_state_kernel<<<(2 * BB * HH + 255) / 256, 256>>>();

    for (int t = 0; t < STEPS; t++) {
        // input select + mlp1_1 (relu)
        select_mlp1_kernel<<<BB * AA, NHID>>>(inputs, w1_1, b1_1, ps, t);

        // mlp1_2: [1280,256] @ [256,256]^T -> g_xin (relu). layout of
        // [B,A,NHID] row-major == [B,H] row-major, so no reshape needed.
        gemm_dual_kernel<<<dim3(NHID / GBN, (BB * AA) / GBM, 1), 128>>>(
            px1, w1_2, b1_2, pxin,
            px1, w1_2, b1_2, pxin, NHID, NHID, 1);

        for (int l = 0; l < 2; l++) {
            const float* hcur = ph + (size_t)l * BB * HH;
            // fused dual GEMM: z=0: x@Wih^T + b_ih -> g_gx ; z=1: h@Whh^T + b_hh -> g_gh
            gemm_dual_kernel<<<dim3(H4 / GBN, BB / GBM, 2), 128>>>(
                pxin, w_ih + (size_t)l * H4 * HH, b_ih + (size_t)l * H4, pgx,
                hcur, w_hh + (size_t)l * H4 * HH, b_hh + (size_t)l * H4, pgh,
                H4, HH, 0);
            lstm_pointwise_kernel<<<(BB * HH) / 256, 256>>>(l);
        }

        // mlp2_1: [256,1280] @ [1280,1280]^T -> g_y (relu)
        gemm_dual_kernel<<<dim3(HH / GBN, BB / GBM, 1), 128>>>(
            pxin, w2_1, b2_1, py,
            pxin, w2_1, b2_1, py, HH, HH, 1);

        // mlp2_2 + residual + write output slice t, update prev_out
        final_kernel<<<(BB * 20 * 32) / 256, 256>>>(w2_2, b2_2, out, t);
    }
}

// round 12
// speedup vs baseline: 1.0001x; 1.0001x over previous
#include <cuda_runtime.h>
#include <cuda_bf16.h>
#include <cstdint>

// Problem constants
#define BB    256
#define AA    5
#define TT    64
#define NINp  4
#define NHID  256
#define HH    1280
#define H4    5120
#define STEPS 63

// ---------------- persistent device scratch (allocation-free) ----------------
__device__ float g_h[2 * BB * HH];       // LSTM hidden states (2 layers)
__device__ float g_c[2 * BB * HH];       // LSTM cell states
__device__ float g_x1[BB * AA * NHID];   // mlp1_1 output  [1280,256]
__device__ float g_xin[BB * HH];         // current activation [256,1280]
__device__ float g_y[BB * HH];           // mlp2_1 output
__device__ float g_gx[BB * H4];          // gates from input GEMM
__device__ float g_gh[BB * H4];          // gates from hidden GEMM
__device__ float g_ins[BB * AA * NINp];  // this step's network input
__device__ float g_prev[BB * AA * NINp]; // previous step's output

__device__ __forceinline__ float sigmoidf_(float x) { return 1.0f / (1.0f + expf(-x)); }

// ---------------- state reset (must run every kernel_launch) ----------------
__global__ void zero_state_kernel() {
    int idx = blockIdx.x * blockDim.x + threadIdx.x;
    if (idx < 2 * BB * HH) { g_h[idx] = 0.0f; g_c[idx] = 0.0f; }
    if (idx < BB * AA * NINp) g_prev[idx] = 0.0f;
}

// ---------------- input select + mlp1_1 (K=4, tiny) ----------------
// grid: 1280 blocks (one per (b,a) row), 256 threads (one per NHID col)
__global__ void select_mlp1_kernel(const float* __restrict__ inputs,
                                   const float* __restrict__ w1_1,
                                   const float* __restrict__ b1_1,
                                   const int*   __restrict__ ps_ptr,
                                   int t) {
    int row = blockIdx.x;   // b*5 + a
    int c   = threadIdx.x;  // 0..255
    __shared__ float ins_s[NINp];
    if (c < NINp) {
        int ps = ps_ptr[0];
        // robust against the scalar being stored as float bits
        if (ps < 1 || ps > 1000000) ps = (int)__int_as_float(ps);
        if (ps < 1) ps = 1;
        float v;
        if ((t % ps) == 0) v = inputs[(row * TT + t) * NINp + c];
        else               v = g_prev[row * NINp + c];
        ins_s[c] = v;
        g_ins[row * NINp + c] = v;
    }
    __syncthreads();
    float acc = b1_1[c];
#pragma unroll
    for (int k = 0; k < NINp; k++) acc = fmaf(ins_s[k], w1_1[c * NINp + k], acc);
    g_x1[row * NHID + c] = fmaxf(acc, 0.0f);
}

// ---------------- generic fp32 GEMM: C = act(A @ B^T + bias) ----------------
// A: [M,K] row-major   B: [N,K] row-major   C: [M,N]
// blockIdx.z selects operand set 0/1 (dual GEMM fused into one launch so
// both LSTM matmuls share the chip in a single wave).
// Tile 64x64, BK=16, 128 threads, per-thread 4x8 register tile.
#define GBM 64
#define GBN 64
#define GBK 16

__global__ __launch_bounds__(128)
void gemm_dual_kernel(const float* __restrict__ A0, const float* __restrict__ B0,
                      const float* __restrict__ bias0, float* __restrict__ C0,
                      const float* __restrict__ A1, const float* __restrict__ B1,
                      const float* __restrict__ bias1, float* __restrict__ C1,
                      int N, int K, int relu) {
    const float* A;  const float* Bm; const float* bias; float* C;
    if (blockIdx.z == 0) { A = A0; Bm = B0; bias = bias0; C = C0; }
    else                 { A = A1; Bm = B1; bias = bias1; C = C1; }

    const int nb = blockIdx.x * GBN;
    const int mb = blockIdx.y * GBM;

    __shared__ __align__(16) float As[GBK][GBM + 4];  // k-major, padded
    __shared__ __align__(16) float Bs[GBK][GBN + 4];

    const int tid = threadIdx.x;           // 0..127
    const int tn  = tid & 7;               // 8 col groups
    const int tm  = tid >> 3;              // 16 row groups
    const int m0  = tm * 4;                // thread's 4 rows
    const int n0  = tn * 8;                // thread's 8 cols

    float acc[4][8];
#pragma unroll
    for (int i = 0; i < 4; i++)
#pragma unroll
        for (int j = 0; j < 8; j++) acc[i][j] = 0.0f;

    for (int kt = 0; kt < K; kt += GBK) {
        // load 64x16 A-tile and 64x16 B-tile (each 256 float4, 2 per thread)
#pragma unroll
        for (int it = 0; it < 2; ++it) {
            int f   = it * 128 + tid;
            int row = f >> 2;
            int k4  = (f & 3) << 2;
            float4 va = *reinterpret_cast<const float4*>(A  + (size_t)(mb + row) * K + kt + k4);
            As[k4 + 0][row] = va.x; As[k4 + 1][row] = va.y;
            As[k4 + 2][row] = va.z; As[k4 + 3][row] = va.w;
            float4 vb = *reinterpret_cast<const float4*>(Bm + (size_t)(nb + row) * K + kt + k4);
            Bs[k4 + 0][row] = vb.x; Bs[k4 + 1][row] = vb.y;
            Bs[k4 + 2][row] = vb.z; Bs[k4 + 3][row] = vb.w;
        }
        __syncthreads();
#pragma unroll
        for (int k = 0; k < GBK; ++k) {
            float4 a4 = *reinterpret_cast<const float4*>(&As[k][m0]);
            float4 b4 = *reinterpret_cast<const float4*>(&Bs[k][n0]);
            float4 b5 = *reinterpret_cast<const float4*>(&Bs[k][n0 + 4]);
            float a[4] = {a4.x, a4.y, a4.z, a4.w};
            float b[8] = {b4.x, b4.y, b4.z, b4.w, b5.x, b5.y, b5.z, b5.w};
#pragma unroll
            for (int i = 0; i < 4; i++)
#pragma unroll
                for (int j = 0; j < 8; j++)
                    acc[i][j] = fmaf(a[i], b[j], acc[i][j]);
        }
        __syncthreads();
    }

    // epilogue
    float bv[8];
#pragma unroll
    for (int j = 0; j < 8; j++) bv[j] = bias ? bias[nb + n0 + j] : 0.0f;
#pragma unroll
    for (int i = 0; i < 4; i++) {
        float* crow = C + (size_t)(mb + m0 + i) * N + nb + n0;
#pragma unroll
        for (int j = 0; j < 8; j++) {
            float v = acc[i][j] + bv[j];
            if (relu) v = fmaxf(v, 0.0f);
            crow[j] = v;
        }
    }
}

// ---------------- LSTM gate pointwise ----------------
// gates = g_gx + g_gh, PyTorch order i,f,g,o along N
__global__ void lstm_pointwise_kernel(int l) {
    int idx = blockIdx.x * blockDim.x + threadIdx.x;  // < BB*HH
    int m = idx / HH;
    int j = idx - m * HH;
    size_t gb = (size_t)m * H4 + j;
    float gi = g_gx[gb]          + g_gh[gb];
    float gf = g_gx[gb + HH]     + g_gh[gb + HH];
    float gg = g_gx[gb + 2 * HH] + g_gh[gb + 2 * HH];
    float go = g_gx[gb + 3 * HH] + g_gh[gb + 3 * HH];
    int off = l * BB * HH + idx;
    float cn = sigmoidf_(gf) * g_c[off] + sigmoidf_(gi) * tanhf(gg);
    float hn = sigmoidf_(go) * tanhf(cn);
    g_c[off]  = cn;
    g_h[off]  = hn;
    g_xin[idx] = hn;   // input to next layer / mlp2
}

// ---------------- mlp2_2 + residual + output ----------------
// one warp per (m,n) output; 256*20 = 5120 warps
__global__ void final_kernel(const float* __restrict__ w2_2,
                             const float* __restrict__ b2_2,
                             float* __restrict__ out, int t) {
    int gtid = blockIdx.x * blockDim.x + threadIdx.x;
    int w    = gtid >> 5;
    int lane = gtid & 31;
    if (w >= BB * 20) return;
    int m = w / 20;
    int n = w - m * 20;
    const float* yr = g_y  + (size_t)m * HH;
    const float* wr = w2_2 + (size_t)n * HH;
    float acc = 0.0f;
#pragma unroll 8
    for (int k = lane; k < HH; k += 32) acc = fmaf(yr[k], wr[k], acc);
#pragma unroll
    for (int s = 16; s; s >>= 1) acc += __shfl_xor_sync(0xffffffffu, acc, s);
    if (lane == 0) {
        float v = acc + b2_2[n] + g_ins[m * 20 + n];
        int a  = n >> 2;
        int nn = n & 3;
        out[((m * AA + a) * STEPS + t) * NINp + nn] = v;
        g_prev[m * 20 + n] = v;
    }
}

// ---------------- host launcher (graph-capturable, allocation-free) ----------------
extern "C" void kernel_launch(void* const* d_in, const int* in_sizes, int n_in,
                              void* d_out, int out_size) {
    const float* inputs = (const float*)d_in[0];
    const float* w1_1   = (const float*)d_in[1];
    const float* b1_1   = (const float*)d_in[2];
    const float* w1_2   = (const float*)d_in[3];
    const float* b1_2   = (const float*)d_in[4];
    const float* w_ih   = (const float*)d_in[5];
    const float* w_hh   = (const float*)d_in[6];
    const float* b_ih   = (const float*)d_in[7];
    const float* b_hh   = (const float*)d_in[8];
    const float* w2_1   = (const float*)d_in[9];
    const float* b2_1   = (const float*)d_in[10];
    const float* w2_2   = (const float*)d_in[11];
    const float* b2_2   = (const float*)d_in[12];
    const int*   ps     = (const int*)d_in[13];
    float* out = (float*)d_out;

    float *ph, *pc, *px1, *pxin, *py, *pgx, *pgh;
    cudaGetSymbolAddress((void**)&ph,   g_h);
    cudaGetSymbolAddress((void**)&pc,   g_c);
    cudaGetSymbolAddress((void**)&px1,  g_x1);
    cudaGetSymbolAddress((void**)&pxin, g_xin);
    cudaGetSymbolAddress((void**)&py,   g_y);
    cudaGetSymbolAddress((void**)&pgx,  g_gx);
    cudaGetSymbolAddress((void**)&pgh,  g_gh);

    // reset recurrent state every launch (deterministic across graph replays)
    zero_state_kernel<<<(2 * BB * HH + 255) / 256, 256>>>();

    for (int t = 0; t < STEPS; t++) {
        // input select + mlp1_1 (relu)
        select_mlp1_kernel<<<BB * AA, NHID>>>(inputs, w1_1, b1_1, ps, t);

        // mlp1_2: [1280,256] @ [256,256]^T -> g_xin (relu). layout of
        // [B,A,NHID] row-major == [B,H] row-major, so no reshape needed.
        gemm_dual_kernel<<<dim3(NHID / GBN, (BB * AA) / GBM, 1), 128>>>(
            px1, w1_2, b1_2, pxin,
            px1, w1_2, b1_2, pxin, NHID, NHID, 1);

        for (int l = 0; l < 2; l++) {
            const float* hcur = ph + (size_t)l * BB * HH;
            // fused dual GEMM: z=0: x@Wih^T + b_ih -> g_gx ; z=1: h@Whh^T + b_hh -> g_gh
            gemm_dual_kernel<<<dim3(H4 / GBN, BB / GBM, 2), 128>>>(
                pxin, w_ih + (size_t)l * H4 * HH, b_ih + (size_t)l * H4, pgx,
                hcur, w_hh + (size_t)l * H4 * HH, b_hh + (size_t)l * H4, pgh,
                H4, HH, 0);
            lstm_pointwise_kernel<<<(BB * HH) / 256, 256>>>(l);
        }

        // mlp2_1: [256,1280] @ [1280,1280]^T -> g_y (relu)
        gemm_dual_kernel<<<dim3(HH / GBN, BB / GBM, 1), 128>>>(
            pxin, w2_1, b2_1, py,
            pxin, w2_1, b2_1, py, HH, HH, 1);

        // mlp2_2 + residual + write output slice t, update prev_out
        final_kernel<<<(BB * 20 * 32) / 256, 256>>>(w2_2, b2_2, out, t);
    }
}

// round 13
// speedup vs baseline: 1.0006x; 1.0004x over previous
#include <cuda_runtime.h>
#include <cuda_bf16.h>
#include <cstdint>

// Problem constants
#define BB    256
#define AA    5
#define TT    64
#define NINp  4
#define NHID  256
#define HH    1280
#define H4    5120
#define STEPS 63

// ---------------- persistent device scratch (allocation-free) ----------------
__device__ float g_h[2 * BB * HH];       // LSTM hidden states (2 layers)
__device__ float g_c[2 * BB * HH];       // LSTM cell states
__device__ float g_x1[BB * AA * NHID];   // mlp1_1 output  [1280,256]
__device__ float g_xin[BB * HH];         // current activation [256,1280]
__device__ float g_y[BB * HH];           // mlp2_1 output
__device__ float g_gx[BB * H4];          // gates from input GEMM
__device__ float g_gh[BB * H4];          // gates from hidden GEMM
__device__ float g_ins[BB * AA * NINp];  // this step's network input
__device__ float g_prev[BB * AA * NINp]; // previous step's output

__device__ __forceinline__ float sigmoidf_(float x) { return 1.0f / (1.0f + expf(-x)); }

// ---------------- state reset (must run every kernel_launch) ----------------
__global__ void zero_state_kernel() {
    int idx = blockIdx.x * blockDim.x + threadIdx.x;
    if (idx < 2 * BB * HH) { g_h[idx] = 0.0f; g_c[idx] = 0.0f; }
    if (idx < BB * AA * NINp) g_prev[idx] = 0.0f;
}

// ---------------- input select + mlp1_1 (K=4, tiny) ----------------
// grid: 1280 blocks (one per (b,a) row), 256 threads (one per NHID col)
__global__ void select_mlp1_kernel(const float* __restrict__ inputs,
                                   const float* __restrict__ w1_1,
                                   const float* __restrict__ b1_1,
                                   const int*   __restrict__ ps_ptr,
                                   int t) {
    int row = blockIdx.x;   // b*5 + a
    int c   = threadIdx.x;  // 0..255
    __shared__ float ins_s[NINp];
    if (c < NINp) {
        int ps = ps_ptr[0];
        // robust against the scalar being stored as float bits
        if (ps < 1 || ps > 1000000) ps = (int)__int_as_float(ps);
        if (ps < 1) ps = 1;
        float v;
        if ((t % ps) == 0) v = inputs[(row * TT + t) * NINp + c];
        else               v = g_prev[row * NINp + c];
        ins_s[c] = v;
        g_ins[row * NINp + c] = v;
    }
    __syncthreads();
    float acc = b1_1[c];
#pragma unroll
    for (int k = 0; k < NINp; k++) acc = fmaf(ins_s[k], w1_1[c * NINp + k], acc);
    g_x1[row * NHID + c] = fmaxf(acc, 0.0f);
}

// ---------------- generic fp32 GEMM: C = act(A @ B^T + bias) ----------------
// A: [M,K] row-major   B: [N,K] row-major   C: [M,N]
// blockIdx.z selects operand set 0/1 (dual GEMM fused into one launch so
// both LSTM matmuls share the chip in a single wave).
// Tile 64x64, BK=16, 128 threads, per-thread 4x8 register tile.
#define GBM 64
#define GBN 64
#define GBK 16

__global__ __launch_bounds__(128)
void gemm_dual_kernel(const float* __restrict__ A0, const float* __restrict__ B0,
                      const float* __restrict__ bias0, float* __restrict__ C0,
                      const float* __restrict__ A1, const float* __restrict__ B1,
                      const float* __restrict__ bias1, float* __restrict__ C1,
                      int N, int K, int relu) {
    const float* A;  const float* Bm; const float* bias; float* C;
    if (blockIdx.z == 0) { A = A0; Bm = B0; bias = bias0; C = C0; }
    else                 { A = A1; Bm = B1; bias = bias1; C = C1; }

    const int nb = blockIdx.x * GBN;
    const int mb = blockIdx.y * GBM;

    __shared__ __align__(16) float As[GBK][GBM + 4];  // k-major, padded
    __shared__ __align__(16) float Bs[GBK][GBN + 4];

    const int tid = threadIdx.x;           // 0..127
    const int tn  = tid & 7;               // 8 col groups
    const int tm  = tid >> 3;              // 16 row groups
    const int m0  = tm * 4;                // thread's 4 rows
    const int n0  = tn * 8;                // thread's 8 cols

    float acc[4][8];
#pragma unroll
    for (int i = 0; i < 4; i++)
#pragma unroll
        for (int j = 0; j < 8; j++) acc[i][j] = 0.0f;

    for (int kt = 0; kt < K; kt += GBK) {
        // load 64x16 A-tile and 64x16 B-tile (each 256 float4, 2 per thread)
#pragma unroll
        for (int it = 0; it < 2; ++it) {
            int f   = it * 128 + tid;
            int row = f >> 2;
            int k4  = (f & 3) << 2;
            float4 va = *reinterpret_cast<const float4*>(A  + (size_t)(mb + row) * K + kt + k4);
            As[k4 + 0][row] = va.x; As[k4 + 1][row] = va.y;
            As[k4 + 2][row] = va.z; As[k4 + 3][row] = va.w;
            float4 vb = *reinterpret_cast<const float4*>(Bm + (size_t)(nb + row) * K + kt + k4);
            Bs[k4 + 0][row] = vb.x; Bs[k4 + 1][row] = vb.y;
            Bs[k4 + 2][row] = vb.z; Bs[k4 + 3][row] = vb.w;
        }
        __syncthreads();
#pragma unroll
        for (int k = 0; k < GBK; ++k) {
            float4 a4 = *reinterpret_cast<const float4*>(&As[k][m0]);
            float4 b4 = *reinterpret_cast<const float4*>(&Bs[k][n0]);
            float4 b5 = *reinterpret_cast<const float4*>(&Bs[k][n0 + 4]);
            float a[4] = {a4.x, a4.y, a4.z, a4.w};
            float b[8] = {b4.x, b4.y, b4.z, b4.w, b5.x, b5.y, b5.z, b5.w};
#pragma unroll
            for (int i = 0; i < 4; i++)
#pragma unroll
                for (int j = 0; j < 8; j++)
                    acc[i][j] = fmaf(a[i], b[j], acc[i][j]);
        }
        __syncthreads();
    }

    // epilogue
    float bv[8];
#pragma unroll
    for (int j = 0; j < 8; j++) bv[j] = bias ? bias[nb + n0 + j] : 0.0f;
#pragma unroll
    for (int i = 0; i < 4; i++) {
        float* crow = C + (size_t)(mb + m0 + i) * N + nb + n0;
#pragma unroll
        for (int j = 0; j < 8; j++) {
            float v = acc[i][j] + bv[j];
            if (relu) v = fmaxf(v, 0.0f);
            crow[j] = v;
        }
    }
}

// ---------------- LSTM gate pointwise ----------------
// gates = g_gx + g_gh, PyTorch order i,f,g,o along N
__global__ void lstm_pointwise_kernel(int l) {
    int idx = blockIdx.x * blockDim.x + threadIdx.x;  // < BB*HH
    int m = idx / HH;
    int j = idx - m * HH;
    size_t gb = (size_t)m * H4 + j;
    float gi = g_gx[gb]          + g_gh[gb];
    float gf = g_gx[gb + HH]     + g_gh[gb + HH];
    float gg = g_gx[gb + 2 * HH] + g_gh[gb + 2 * HH];
    float go = g_gx[gb + 3 * HH] + g_gh[gb + 3 * HH];
    int off = l * BB * HH + idx;
    float cn = sigmoidf_(gf) * g_c[off] + sigmoidf_(gi) * tanhf(gg);
    float hn = sigmoidf_(go) * tanhf(cn);
    g_c[off]  = cn;
    g_h[off]  = hn;
    g_xin[idx] = hn;   // input to next layer / mlp2
}

// ---------------- mlp2_2 + residual + output ----------------
// one warp per (m,n) output; 256*20 = 5120 warps
__global__ void final_kernel(const float* __restrict__ w2_2,
                             const float* __restrict__ b2_2,
                             float* __restrict__ out, int t) {
    int gtid = blockIdx.x * blockDim.x + threadIdx.x;
    int w    = gtid >> 5;
    int lane = gtid & 31;
    if (w >= BB * 20) return;
    int m = w / 20;
    int n = w - m * 20;
    const float* yr = g_y  + (size_t)m * HH;
    const float* wr = w2_2 + (size_t)n * HH;
    float acc = 0.0f;
#pragma unroll 8
    for (int k = lane; k < HH; k += 32) acc = fmaf(yr[k], wr[k], acc);
#pragma unroll
    for (int s = 16; s; s >>= 1) acc += __shfl_xor_sync(0xffffffffu, acc, s);
    if (lane == 0) {
        float v = acc + b2_2[n] + g_ins[m * 20 + n];
        int a  = n >> 2;
        int nn = n & 3;
        out[((m * AA + a) * STEPS + t) * NINp + nn] = v;
        g_prev[m * 20 + n] = v;
    }
}

// ---------------- host launcher (graph-capturable, allocation-free) ----------------
extern "C" void kernel_launch(void* const* d_in, const int* in_sizes, int n_in,
                              void* d_out, int out_size) {
    const float* inputs = (const float*)d_in[0];
    const float* w1_1   = (const float*)d_in[1];
    const float* b1_1   = (const float*)d_in[2];
    const float* w1_2   = (const float*)d_in[3];
    const float* b1_2   = (const float*)d_in[4];
    const float* w_ih   = (const float*)d_in[5];
    const float* w_hh   = (const float*)d_in[6];
    const float* b_ih   = (const float*)d_in[7];
    const float* b_hh   = (const float*)d_in[8];
    const float* w2_1   = (const float*)d_in[9];
    const float* b2_1   = (const float*)d_in[10];
    const float* w2_2   = (const float*)d_in[11];
    const float* b2_2   = (const float*)d_in[12];
    const int*   ps     = (const int*)d_in[13];
    float* out = (float*)d_out;

    float *ph, *pc, *px1, *pxin, *py, *pgx, *pgh;
    cudaGetSymbolAddress((void**)&ph,   g_h);
    cudaGetSymbolAddress((void**)&pc,   g_c);
    cudaGetSymbolAddress((void**)&px1,  g_x1);
    cudaGetSymbolAddress((void**)&pxin, g_xin);
    cudaGetSymbolAddress((void**)&py,   g_y);
    cudaGetSymbolAddress((void**)&pgx,  g_gx);
    cudaGetSymbolAddress((void**)&pgh,  g_gh);

    // reset recurrent state every launch (deterministic across graph replays)
    zero_state_kernel<<<(2 * BB * HH + 255) / 256, 256>>>();

    for (int t = 0; t < STEPS; t++) {
        // input select + mlp1_1 (relu)
        select_mlp1_kernel<<<BB * AA, NHID>>>(inputs, w1_1, b1_1, ps, t);

        // mlp1_2: [1280,256] @ [256,256]^T -> g_xin (relu). layout of
        // [B,A,NHID] row-major == [B,H] row-major, so no reshape needed.
        gemm_dual_kernel<<<dim3(NHID / GBN, (BB * AA) / GBM, 1), 128>>>(
            px1, w1_2, b1_2, pxin,
            px1, w1_2, b1_2, pxin, NHID, NHID, 1);

        for (int l = 0; l < 2; l++) {
            const float* hcur = ph + (size_t)l * BB * HH;
            // fused dual GEMM: z=0: x@Wih^T + b_ih -> g_gx ; z=1: h@Whh^T + b_hh -> g_gh
            gemm_dual_kernel<<<dim3(H4 / GBN, BB / GBM, 2), 128>>>(
                pxin, w_ih + (size_t)l * H4 * HH, b_ih + (size_t)l * H4, pgx,
                hcur, w_hh + (size_t)l * H4 * HH, b_hh + (size_t)l * H4, pgh,
                H4, HH, 0);
            lstm_pointwise_kernel<<<(BB * HH) / 256, 256>>>(l);
        }

        // mlp2_1: [256,1280] @ [1280,1280]^T -> g_y (relu)
        gemm_dual_kernel<<<dim3(HH / GBN, BB / GBM, 1), 128>>>(
            pxin, w2_1, b2_1, py,
            pxin, w2_1, b2_1, py, HH, HH, 1);

        // mlp2_2 + residual + write output slice t, update prev_out
        final_kernel<<<(BB * 20 * 32) / 256, 256>>>(w2_2, b2_2, out, t);
    }
}